// round 17
// baseline (speedup 1.0000x reference)
#include <cuda_runtime.h>
#include <math.h>

#define NN 32768
#define FF 64
#define HH 4
#define HFD 256
#define ESZ 524288
#define EGZ 524288
#define GG 64
#define NCC 10
#define BNEPS 1e-5f

// ---------------- float scratch arena ----------------------------------------
#define O_B0     0
#define O_BR     (O_B0 + NN*FF)
#define O_X      (O_BR + 3*NN*FF)
#define O_H      (O_X + 3*NN*FF)
#define O_ATT    (O_H + NN*HFD)
#define O_AS     (O_ATT + NN*HFD)
#define O_AD     (O_AS + NN*HH)
#define O_MX     (O_AD + NN*HH)        // per-node softmax max [N,4]
#define O_SEXP   (O_MX + NN*HH)
#define O_INV    (O_SEXP + NN*HH)
#define O_CA     (O_INV + NN*HH)       // csr attrs for scatter sets 0..3 [4*E]
#define O_Z      (O_CA + 4*ESZ)        // 4 branch z buffers
#define O_STATS  (O_Z + 4*NN*FF)
#define O_POOL   (O_STATS + 512)
#define ARENA_SZ (O_POOL + GG*FF)

__device__ __align__(256) float g_arena[ARENA_SZ];

// ---------------- int scratch arena -------------------------------------------
// 5 CSR sets: slot 0 = GAT edge graph (eidx), slots 1..4 = scatter idx 0..3
#define I_DEG  0
#define I_CUR  (I_DEG + 5*NN)
#define I_RP   (I_CUR + 5*NN)
#define I_CSRE (I_RP + 5*NN)
#define I_CSR0 (I_CSRE + EGZ)          // 4*E for scatter sets
#define I_BSUM (I_CSR0 + 4*ESZ)
#define IARENA_SZ (I_BSUM + 5*128)

__device__ __align__(256) int g_iarena[IARENA_SZ];

// ---------------- helpers -----------------------------------------------------
__device__ __forceinline__ void red4(float* a, float4 v) {
    asm volatile("red.global.add.v4.f32 [%0], {%1,%2,%3,%4};"
                 :: "l"(a), "f"(v.x), "f"(v.y), "f"(v.z), "f"(v.w) : "memory");
}
__device__ __forceinline__ float lrelu(float v) { return v > 0.f ? v : 0.2f * v; }
__device__ __forceinline__ float eluf(float v)  { return v > 0.f ? v : __expf(v) - 1.f; }
__device__ __forceinline__ float tf32r(float f) {
    unsigned o;
    asm("cvt.rna.tf32.f32 %0, %1;" : "=r"(o) : "f"(f));
    return __uint_as_float(o);
}
__device__ __forceinline__ void mma8(float* d, float a0, float a1, float a2, float a3,
                                     float b0, float b1) {
    asm volatile(
        "mma.sync.aligned.m16n8k8.row.col.f32.tf32.tf32.f32 "
        "{%0,%1,%2,%3}, {%4,%5,%6,%7}, {%8,%9}, {%0,%1,%2,%3};"
        : "+f"(d[0]), "+f"(d[1]), "+f"(d[2]), "+f"(d[3])
        : "r"(__float_as_uint(a0)), "r"(__float_as_uint(a1)),
          "r"(__float_as_uint(a2)), "r"(__float_as_uint(a3)),
          "r"(__float_as_uint(b0)), "r"(__float_as_uint(b1)));
}
// online-softmax accumulate: (m,s) <- combine with value e (weight 1)
__device__ __forceinline__ void osm_acc(float& m, float& s, float e) {
    if (e <= m) {
        s += __expf(e - m);
    } else {
        s = s * __expf(m - e) + 1.f;
        m = e;
    }
}
// combine two (m,s) pairs
__device__ __forceinline__ void osm_merge(float& m, float& s, float om, float os) {
    float nm = fmaxf(m, om);
    s = s * __expf(m - nm) + os * __expf(om - nm);
    m = nm;
}

// ---------------- CSR build (5 sets via grid.y) -------------------------------
__global__ __launch_bounds__(256) void k_hist5(
    const int* __restrict__ eidx, const int* __restrict__ sidx, int* __restrict__ DEG)
{
    int y = blockIdx.y;
    const int* dstp = (y == 0) ? (eidx + EGZ) : (sidx + (y - 1) * 2 * ESZ + ESZ);
    int e = blockIdx.x * 256 + threadIdx.x;
    atomicAdd(&DEG[y * NN + dstp[e]], 1);
}

__global__ __launch_bounds__(256) void k_blocksum5(
    const int* __restrict__ DEG, int* __restrict__ BSUM)
{
    __shared__ int sh[256];
    int y = blockIdx.y;
    int t = threadIdx.x;
    sh[t] = DEG[y * NN + blockIdx.x * 256 + t];
    __syncthreads();
#pragma unroll
    for (int off = 128; off; off >>= 1) {
        if (t < off) sh[t] += sh[t + off];
        __syncthreads();
    }
    if (t == 0) BSUM[y * 128 + blockIdx.x] = sh[0];
}

__global__ __launch_bounds__(128) void k_scanbs5(int* __restrict__ BSUM)
{
    __shared__ int sh[128];
    int* bsum = BSUM + blockIdx.x * 128;
    int t = threadIdx.x;
    int v = bsum[t];
    sh[t] = v;
    __syncthreads();
#pragma unroll
    for (int off = 1; off < 128; off <<= 1) {
        int u = (t >= off) ? sh[t - off] : 0;
        __syncthreads();
        sh[t] += u;
        __syncthreads();
    }
    bsum[t] = sh[t] - v;
}

__global__ __launch_bounds__(256) void k_scanout5(
    const int* __restrict__ DEG, const int* __restrict__ BSUM,
    int* __restrict__ RP, int* __restrict__ CUR)
{
    __shared__ int sh[256];
    int y = blockIdx.y;
    int t = threadIdx.x;
    int g = blockIdx.x * 256 + t;
    int v = DEG[y * NN + g];
    sh[t] = v;
    __syncthreads();
#pragma unroll
    for (int off = 1; off < 256; off <<= 1) {
        int u = (t >= off) ? sh[t - off] : 0;
        __syncthreads();
        sh[t] += u;
        __syncthreads();
    }
    int ex = sh[t] - v + BSUM[y * 128 + blockIdx.x];
    RP[y * NN + g] = ex;
    CUR[y * NN + g] = ex;
}

// fill all 5 CSR sets (grid.y = 5): y=0 edge graph, y=1..4 scatter sets 0..3
__global__ __launch_bounds__(256) void k_fill5(
    const int* __restrict__ eidx, const int* __restrict__ sidx,
    const float* __restrict__ sattr,
    int* __restrict__ CUR, int* __restrict__ CSRE,
    int* __restrict__ CSR0, float* __restrict__ CA)
{
    int y = blockIdx.y;
    int e = blockIdx.x * 256 + threadIdx.x;
    if (y == 0) {
        int d = eidx[EGZ + e];
        int p = atomicAdd(&CUR[d], 1);
        CSRE[p] = eidx[e];
    } else {
        int j = y - 1;
        const int* si = sidx + j * 2 * ESZ;
        int d = si[ESZ + e];
        int p = atomicAdd(&CUR[y * NN + d], 1);
        CSR0[j * ESZ + p] = si[e];
        CA[j * ESZ + p] = sattr[j * ESZ + e];
    }
}

// ---------------- gather for scatter sets 1..3 --------------------------------
__global__ __launch_bounds__(256) void k_gatherBR(
    const int* __restrict__ RP, const int* __restrict__ DEG,
    const int* __restrict__ CSR0, const float* __restrict__ CA,
    const float* __restrict__ x, float* __restrict__ brout)
{
    int j = blockIdx.y + 1;                      // scatter set 1..3
    const int* rowptr = RP + (j + 1) * NN;
    const int* deg = DEG + (j + 1) * NN;
    const int* csr = CSR0 + j * ESZ;
    const float* csra = CA + j * ESZ;
    float* outb = brout + (size_t)(j - 1) * NN * FF;

    int t = blockIdx.x * 256 + threadIdx.x;
    int n = t >> 4, q = t & 15;
    int b = rowptr[n], dg = deg[n];
    float4 acc = make_float4(0.f, 0.f, 0.f, 0.f);
    const float4* x4 = (const float4*)x;
    for (int p = b; p < b + dg; p++) {
        int s = csr[p];
        float a = csra[p];
        float4 v = x4[s * 16 + q];
        acc.x += a * v.x; acc.y += a * v.y; acc.z += a * v.z; acc.w += a * v.w;
    }
    ((float4*)outb)[n * 16 + q] = acc;
}

// ---------------- gathers with scatter-set-0 CSR (4 via grid.y) ---------------
__global__ __launch_bounds__(256) void k_gather4(
    const int* __restrict__ RP, const int* __restrict__ DEG,
    const int* __restrict__ CSR0, const float* __restrict__ CA,
    const float* __restrict__ x, const float* __restrict__ brin,
    float* __restrict__ b0out, float* __restrict__ xout)
{
    int br = blockIdx.y;
    const float* xin = (br == 0) ? x : brin + (size_t)(br - 1) * NN * FF;
    float* outb = (br == 0) ? b0out : xout + (size_t)(br - 1) * NN * FF;
    int doAbs = (br > 0);
    const int* rowptr = RP + NN;                 // set 0 lives in slot 1
    const int* deg = DEG + NN;
    const int* csr = CSR0;
    const float* csra = CA;

    int t = blockIdx.x * 256 + threadIdx.x;
    int n = t >> 4, q = t & 15;
    int b = rowptr[n], dg = deg[n];
    float4 acc = make_float4(0.f, 0.f, 0.f, 0.f);
    const float4* xin4 = (const float4*)xin;
    for (int p = b; p < b + dg; p++) {
        int s = csr[p];
        float a = csra[p];
        float4 v = xin4[s * 16 + q];
        if (doAbs) { v.x = fabsf(v.x); v.y = fabsf(v.y); v.z = fabsf(v.z); v.w = fabsf(v.w); }
        acc.x += a * v.x; acc.y += a * v.y; acc.z += a * v.z; acc.w += a * v.w;
    }
    ((float4*)outb)[n * 16 + q] = acc;
}

// ---------------- GEMM1 3xTF32 mma + fused attcoef ----------------------------
__global__ __launch_bounds__(256) void k_gemm_h_mma(
    const float* __restrict__ xin, const float* __restrict__ W,
    const float* __restrict__ asrc, const float* __restrict__ adst,
    float* __restrict__ h, float* __restrict__ as_, float* __restrict__ ad_)
{
    extern __shared__ float sm1[];
    float* As = sm1;              // 64 x 68
    float* Ws = sm1 + 64 * 68;    // 64 x 264
    int t = threadIdx.x;
    int row0 = blockIdx.x * 64;

    for (int i = t; i < 64 * 16; i += 256) {
        int r = i >> 4, c4 = i & 15;
        float4 v = ((const float4*)(xin + (size_t)(row0 + r) * 64))[c4];
        float* dp = &As[r * 68 + c4 * 4];
        dp[0] = v.x; dp[1] = v.y; dp[2] = v.z; dp[3] = v.w;
    }
    const float4* W4 = (const float4*)W;
    for (int i = t; i < 64 * 64; i += 256) {
        int r = i >> 6, c4 = i & 63;
        float4 v = W4[r * 64 + c4];
        float* dp = &Ws[r * 264 + c4 * 4];
        dp[0] = v.x; dp[1] = v.y; dp[2] = v.z; dp[3] = v.w;
    }
    __syncthreads();

    int wid = t >> 5, lane = t & 31;
    int wm = wid & 3, wn = wid >> 2;
    int g = lane >> 2, tg = lane & 3;

    float acc[16][4];
#pragma unroll
    for (int nt = 0; nt < 16; nt++)
#pragma unroll
        for (int c = 0; c < 4; c++) acc[nt][c] = 0.f;

#pragma unroll
    for (int k8 = 0; k8 < 8; k8++) {
        int kb = k8 * 8;
        float v0 = As[(wm * 16 + g) * 68 + kb + tg];
        float v1 = As[(wm * 16 + g + 8) * 68 + kb + tg];
        float v2 = As[(wm * 16 + g) * 68 + kb + tg + 4];
        float v3 = As[(wm * 16 + g + 8) * 68 + kb + tg + 4];
        float ah0 = tf32r(v0), ah1 = tf32r(v1), ah2 = tf32r(v2), ah3 = tf32r(v3);
        float al0 = tf32r(v0 - ah0), al1 = tf32r(v1 - ah1);
        float al2 = tf32r(v2 - ah2), al3 = tf32r(v3 - ah3);
#pragma unroll
        for (int nt = 0; nt < 16; nt++) {
            int n0 = wn * 128 + nt * 8;
            float w0 = Ws[(kb + tg) * 264 + n0 + g];
            float w1 = Ws[(kb + tg + 4) * 264 + n0 + g];
            float bh0 = tf32r(w0), bh1 = tf32r(w1);
            float bl0 = tf32r(w0 - bh0), bl1 = tf32r(w1 - bh1);
            mma8(acc[nt], al0, al1, al2, al3, bh0, bh1);
            mma8(acc[nt], ah0, ah1, ah2, ah3, bl0, bl1);
            mma8(acc[nt], ah0, ah1, ah2, ah3, bh0, bh1);
        }
    }

    int r0 = row0 + wm * 16 + g;
    int r1 = r0 + 8;
#pragma unroll
    for (int nt = 0; nt < 16; nt++) {
        int n0 = wn * 128 + nt * 8 + tg * 2;
        *(float2*)&h[(size_t)r0 * 256 + n0] = make_float2(acc[nt][0], acc[nt][1]);
        *(float2*)&h[(size_t)r1 * 256 + n0] = make_float2(acc[nt][2], acc[nt][3]);
    }

    float sa[2][2] = {{0.f, 0.f}, {0.f, 0.f}};
    float sd[2][2] = {{0.f, 0.f}, {0.f, 0.f}};
#pragma unroll
    for (int nt = 0; nt < 16; nt++) {
        int hsel = nt >> 3;
        int hd = wn * 2 + hsel;
        int cm = (nt & 7) * 8 + tg * 2;
        float wa0 = asrc[hd * 64 + cm], wa1 = asrc[hd * 64 + cm + 1];
        float wd0 = adst[hd * 64 + cm], wd1 = adst[hd * 64 + cm + 1];
        sa[hsel][0] += acc[nt][0] * wa0 + acc[nt][1] * wa1;
        sa[hsel][1] += acc[nt][2] * wa0 + acc[nt][3] * wa1;
        sd[hsel][0] += acc[nt][0] * wd0 + acc[nt][1] * wd1;
        sd[hsel][1] += acc[nt][2] * wd0 + acc[nt][3] * wd1;
    }
#pragma unroll
    for (int o = 1; o <= 2; o <<= 1) {
#pragma unroll
        for (int hs = 0; hs < 2; hs++)
#pragma unroll
            for (int rr = 0; rr < 2; rr++) {
                sa[hs][rr] += __shfl_xor_sync(0xffffffffu, sa[hs][rr], o);
                sd[hs][rr] += __shfl_xor_sync(0xffffffffu, sd[hs][rr], o);
            }
    }
    if (tg == 0) {
        as_[r0 * 4 + wn * 2 + 0] = sa[0][0];
        as_[r1 * 4 + wn * 2 + 0] = sa[0][1];
        as_[r0 * 4 + wn * 2 + 1] = sa[1][0];
        as_[r1 * 4 + wn * 2 + 1] = sa[1][1];
        ad_[r0 * 4 + wn * 2 + 0] = sd[0][0];
        ad_[r1 * 4 + wn * 2 + 0] = sd[0][1];
        ad_[r0 * 4 + wn * 2 + 1] = sd[1][0];
        ad_[r1 * 4 + wn * 2 + 1] = sd[1][1];
    }
}

// ---------------- GEMM2 3xTF32 mma + fused BN stats ---------------------------
__global__ __launch_bounds__(256) void k_gemm_z_mma(
    const float* __restrict__ att, const float* __restrict__ bias,
    const float* __restrict__ W, float* __restrict__ z, float* __restrict__ stats)
{
    __shared__ float As[64 * 68];
    __shared__ float Ws[64 * 72];
    __shared__ float ssum[64], ssq[64];
    int t = threadIdx.x;
    int row0 = blockIdx.x * 64;
    if (t < 64) { ssum[t] = 0.f; ssq[t] = 0.f; }

    int wid = t >> 5, lane = t & 31;
    int wm = wid & 3, wn = wid >> 2;
    int g = lane >> 2, tg = lane & 3;

    float acc[4][4];
#pragma unroll
    for (int nt = 0; nt < 4; nt++)
#pragma unroll
        for (int c = 0; c < 4; c++) acc[nt][c] = 0.f;

    const float4* att4 = (const float4*)att;
    const float4* bias4 = (const float4*)bias;
    const float4* W4 = (const float4*)W;

    for (int kc = 0; kc < 4; kc++) {
        __syncthreads();
        for (int i = t; i < 64 * 16; i += 256) {
            int r = i >> 4, c4 = i & 15;
            float4 v = att4[(size_t)(row0 + r) * 64 + kc * 16 + c4];
            float4 b = bias4[kc * 16 + c4];
            float* dp = &As[r * 68 + c4 * 4];
            dp[0] = eluf(v.x + b.x); dp[1] = eluf(v.y + b.y);
            dp[2] = eluf(v.z + b.z); dp[3] = eluf(v.w + b.w);
        }
        for (int i = t; i < 64 * 16; i += 256) {
            int r = i >> 4, c4 = i & 15;
            float4 v = W4[(size_t)(kc * 64 + r) * 16 + c4];
            float* dp = &Ws[r * 72 + c4 * 4];
            dp[0] = v.x; dp[1] = v.y; dp[2] = v.z; dp[3] = v.w;
        }
        __syncthreads();
#pragma unroll
        for (int k8 = 0; k8 < 8; k8++) {
            int kb = k8 * 8;
            float v0 = As[(wm * 16 + g) * 68 + kb + tg];
            float v1 = As[(wm * 16 + g + 8) * 68 + kb + tg];
            float v2 = As[(wm * 16 + g) * 68 + kb + tg + 4];
            float v3 = As[(wm * 16 + g + 8) * 68 + kb + tg + 4];
            float ah0 = tf32r(v0), ah1 = tf32r(v1), ah2 = tf32r(v2), ah3 = tf32r(v3);
            float al0 = tf32r(v0 - ah0), al1 = tf32r(v1 - ah1);
            float al2 = tf32r(v2 - ah2), al3 = tf32r(v3 - ah3);
#pragma unroll
            for (int nt = 0; nt < 4; nt++) {
                int n0 = wn * 32 + nt * 8;
                float w0 = Ws[(kb + tg) * 72 + n0 + g];
                float w1 = Ws[(kb + tg + 4) * 72 + n0 + g];
                float bh0 = tf32r(w0), bh1 = tf32r(w1);
                float bl0 = tf32r(w0 - bh0), bl1 = tf32r(w1 - bh1);
                mma8(acc[nt], al0, al1, al2, al3, bh0, bh1);
                mma8(acc[nt], ah0, ah1, ah2, ah3, bl0, bl1);
                mma8(acc[nt], ah0, ah1, ah2, ah3, bh0, bh1);
            }
        }
    }

    int r0 = row0 + wm * 16 + g;
    int r1 = r0 + 8;
#pragma unroll
    for (int nt = 0; nt < 4; nt++) {
        int c = wn * 32 + nt * 8 + tg * 2;
        *(float2*)&z[(size_t)r0 * 64 + c] = make_float2(acc[nt][0], acc[nt][1]);
        *(float2*)&z[(size_t)r1 * 64 + c] = make_float2(acc[nt][2], acc[nt][3]);
        atomicAdd(&ssum[c],     acc[nt][0] + acc[nt][2]);
        atomicAdd(&ssum[c + 1], acc[nt][1] + acc[nt][3]);
        atomicAdd(&ssq[c],      acc[nt][0] * acc[nt][0] + acc[nt][2] * acc[nt][2]);
        atomicAdd(&ssq[c + 1],  acc[nt][1] * acc[nt][1] + acc[nt][3] * acc[nt][3]);
    }
    __syncthreads();
    if (t < 64) {
        atomicAdd(&stats[t], ssum[t]);
        atomicAdd(&stats[FF + t], ssq[t]);
    }
}

// ---------------- single-pass online softmax (warp/node) ----------------------
// writes MX, SEXP, INV only; alphas recomputed inline in aggregation
__global__ __launch_bounds__(256) void k_softmax(
    const int* __restrict__ rowptr, const int* __restrict__ deg, const int* __restrict__ csr,
    const float* __restrict__ as_, const float* __restrict__ ad_,
    float* __restrict__ mx_, float* __restrict__ sexp, float* __restrict__ inv)
{
    int n = blockIdx.x * 8 + (threadIdx.x >> 5);
    int lane = threadIdx.x & 31;
    int b = rowptr[n], dg = deg[n];
    float4 adn = ((const float4*)ad_)[n];
    float4 asn = ((const float4*)as_)[n];
    float4 self;
    self.x = lrelu(asn.x + adn.x); self.y = lrelu(asn.y + adn.y);
    self.z = lrelu(asn.z + adn.z); self.w = lrelu(asn.w + adn.w);

    float4 m = make_float4(-1e30f, -1e30f, -1e30f, -1e30f);
    float4 s = make_float4(0.f, 0.f, 0.f, 0.f);
    for (int j = lane; j < dg; j += 32) {
        float4 sv = ((const float4*)as_)[csr[b + j]];
        osm_acc(m.x, s.x, lrelu(sv.x + adn.x));
        osm_acc(m.y, s.y, lrelu(sv.y + adn.y));
        osm_acc(m.z, s.z, lrelu(sv.z + adn.z));
        osm_acc(m.w, s.w, lrelu(sv.w + adn.w));
    }
#pragma unroll
    for (int o = 16; o; o >>= 1) {
        float om, os;
        om = __shfl_xor_sync(0xffffffffu, m.x, o);
        os = __shfl_xor_sync(0xffffffffu, s.x, o);
        osm_merge(m.x, s.x, om, os);
        om = __shfl_xor_sync(0xffffffffu, m.y, o);
        os = __shfl_xor_sync(0xffffffffu, s.y, o);
        osm_merge(m.y, s.y, om, os);
        om = __shfl_xor_sync(0xffffffffu, m.z, o);
        os = __shfl_xor_sync(0xffffffffu, s.z, o);
        osm_merge(m.z, s.z, om, os);
        om = __shfl_xor_sync(0xffffffffu, m.w, o);
        os = __shfl_xor_sync(0xffffffffu, s.w, o);
        osm_merge(m.w, s.w, om, os);
    }
    if (lane == 0) {
        float4 fm, sex, iv;
        fm.x = fmaxf(m.x, self.x); fm.y = fmaxf(m.y, self.y);
        fm.z = fmaxf(m.z, self.z); fm.w = fmaxf(m.w, self.w);
        sex.x = __expf(self.x - fm.x); sex.y = __expf(self.y - fm.y);
        sex.z = __expf(self.z - fm.z); sex.w = __expf(self.w - fm.w);
        iv.x = 1.f / (s.x * __expf(m.x - fm.x) + sex.x);
        iv.y = 1.f / (s.y * __expf(m.y - fm.y) + sex.y);
        iv.z = 1.f / (s.z * __expf(m.z - fm.z) + sex.z);
        iv.w = 1.f / (s.w * __expf(m.w - fm.w) + sex.w);
        ((float4*)mx_)[n] = fm;
        ((float4*)sexp)[n] = sex;
        ((float4*)inv)[n] = iv;
    }
}

// ---------------- CSR gather aggregation with inline alpha --------------------
__global__ __launch_bounds__(256) void k_aggr(
    const int* __restrict__ rowptr, const int* __restrict__ deg, const int* __restrict__ csr,
    const float* __restrict__ as_, const float* __restrict__ ad_,
    const float* __restrict__ mx_, const float* __restrict__ sexp, const float* __restrict__ inv,
    const float* __restrict__ h, float* __restrict__ att)
{
    int t = blockIdx.x * 256 + threadIdx.x;
    int n = t >> 6, gq = t & 63, hd = gq >> 4;
    int lane = threadIdx.x & 31;
    int srcLane = lane & 16;                 // leader lane of this 16-group
    bool lead = ((lane & 15) == 0);
    int b = rowptr[n], dg = deg[n];
    float sex = sexp[n * 4 + hd];
    float iv  = inv[n * 4 + hd];
    float mxv = mx_[n * 4 + hd];
    float adv = ad_[n * 4 + hd];
    const float4* h4 = (const float4*)h;
    float4 acc = h4[(size_t)n * 64 + gq];
    acc.x *= sex; acc.y *= sex; acc.z *= sex; acc.w *= sex;
    for (int p = b; p < b + dg; p++) {
        int s = csr[p];
        float al = 0.f;
        if (lead) {
            float asv = __ldg(&as_[s * 4 + hd]);
            al = __expf(lrelu(asv + adv) - mxv);
        }
        al = __shfl_sync(0xffffffffu, al, srcLane);
        float4 hv = h4[(size_t)s * 64 + gq];
        acc.x += al * hv.x; acc.y += al * hv.y;
        acc.z += al * hv.z; acc.w += al * hv.w;
    }
    acc.x *= iv; acc.y *= iv; acc.z *= iv; acc.w *= iv;
    ((float4*)att)[(size_t)n * 64 + gq] = acc;
}

// ---------------- fused BN tail: pool += x + sum_br BN(z_br) ------------------
__global__ __launch_bounds__(256) void k_bnfinal(
    const float* __restrict__ Z, const float* __restrict__ stats,
    const float* __restrict__ mlpg, const float* __restrict__ mlpbe,
    const float* __restrict__ x, const int* __restrict__ batch,
    float* __restrict__ pool)
{
    __shared__ float smu[256], srs[256], sbb[256];
    int t = threadIdx.x;
    if (t < 256) {
        int br = t >> 6, f = t & 63;
        float mu = stats[br * 128 + f] * (1.f / NN);
        float var = stats[br * 128 + 64 + f] * (1.f / NN) - mu * mu;
        smu[t] = mu;
        srs[t] = rsqrtf(var + BNEPS) * mlpg[br * 64 + f];
        sbb[t] = mlpbe[br * 64 + f];
    }
    __syncthreads();
    int gidx = blockIdx.x * 256 + t;
    int n = gidx >> 4, q = gidx & 15, f0 = q * 4;
    float4 v = ((const float4*)x)[gidx];
#pragma unroll
    for (int br = 0; br < 4; br++) {
        float4 zv = ((const float4*)Z)[(size_t)br * NN * 16 + gidx];
        int o = br * 64 + f0;
        v.x += (zv.x - smu[o + 0]) * srs[o + 0] + sbb[o + 0];
        v.y += (zv.y - smu[o + 1]) * srs[o + 1] + sbb[o + 1];
        v.z += (zv.z - smu[o + 2]) * srs[o + 2] + sbb[o + 2];
        v.w += (zv.w - smu[o + 3]) * srs[o + 3] + sbb[o + 3];
    }
    red4(pool + batch[n] * 64 + f0, v);
}

// ---------------- fused FC head (single block, 1024 threads) ------------------
__global__ __launch_bounds__(1024) void k_head(
    const float* __restrict__ pool,
    const float* __restrict__ fc1W, const float* __restrict__ fc1b,
    const float* __restrict__ fc1g, const float* __restrict__ fc1be,
    const float* __restrict__ fc2W, const float* __restrict__ fc2b,
    const float* __restrict__ fc2g, const float* __restrict__ fc2be,
    const float* __restrict__ fc3W, const float* __restrict__ fc3b,
    const float* __restrict__ fc3g, const float* __restrict__ fc3be,
    float* __restrict__ out)
{
    extern __shared__ float sm[];
    float* sp = sm;
    float* y1 = sp + 64 * 65;
    float* y2 = y1 + 64 * 257;
    int t = threadIdx.x;

    for (int i = t; i < 64 * 16; i += 1024) {
        int r = i >> 4, c4 = i & 15;
        float4 v = ((const float4*)pool)[i];
        float* dp = &sp[r * 65 + c4 * 4];
        dp[0] = v.x; dp[1] = v.y; dp[2] = v.z; dp[3] = v.w;
    }
    __syncthreads();

    {
        int c = t & 255, rg = t >> 8;
        float accv[16];
        float bb = fc1b[c];
#pragma unroll
        for (int r = 0; r < 16; r++) accv[r] = bb;
        for (int k = 0; k < 64; k++) {
            float w = fc1W[k * 256 + c];
#pragma unroll
            for (int r = 0; r < 16; r++)
                accv[r] += sp[(rg * 16 + r) * 65 + k] * w;
        }
#pragma unroll
        for (int r = 0; r < 16; r++) y1[(rg * 16 + r) * 257 + c] = accv[r];
    }
    __syncthreads();
    if (t < 256) {
        float s = 0.f, ss = 0.f;
#pragma unroll 8
        for (int r = 0; r < 64; r++) { float v = y1[r * 257 + t]; s += v; ss += v * v; }
        float mu = s * (1.f / GG);
        float var = ss * (1.f / GG) - mu * mu;
        sp[t] = mu;
        sp[256 + t] = rsqrtf(var + BNEPS) * fc1g[t];
    }
    __syncthreads();
    for (int i = t; i < 64 * 256; i += 1024) {
        int r = i >> 8, c = i & 255;
        float v = (y1[r * 257 + c] - sp[c]) * sp[256 + c] + fc1be[c];
        y1[r * 257 + c] = fmaxf(v, 0.f);
    }
    __syncthreads();

    {
        int c = t & 127, rg = t >> 7;
        float accv[8];
        float bb = fc2b[c];
#pragma unroll
        for (int r = 0; r < 8; r++) accv[r] = bb;
        for (int k = 0; k < 256; k++) {
            float w = fc2W[k * 128 + c];
#pragma unroll
            for (int r = 0; r < 8; r++)
                accv[r] += y1[(rg * 8 + r) * 257 + k] * w;
        }
#pragma unroll
        for (int r = 0; r < 8; r++) y2[(rg * 8 + r) * 129 + c] = accv[r];
    }
    __syncthreads();
    if (t < 128) {
        float s = 0.f, ss = 0.f;
#pragma unroll 8
        for (int r = 0; r < 64; r++) { float v = y2[r * 129 + t]; s += v; ss += v * v; }
        float mu = s * (1.f / GG);
        float var = ss * (1.f / GG) - mu * mu;
        sp[t] = mu;
        sp[256 + t] = rsqrtf(var + BNEPS) * fc2g[t];
    }
    __syncthreads();
    for (int i = t; i < 64 * 128; i += 1024) {
        int r = i >> 7, c = i & 127;
        float v = (y2[r * 129 + c] - sp[c]) * sp[256 + c] + fc2be[c];
        y2[r * 129 + c] = fmaxf(v, 0.f);
    }
    __syncthreads();

    float* y3 = sp + 1024;
    if (t < 640) {
        int r = t / NCC, c = t % NCC;
        float acc = fc3b[c];
        for (int k = 0; k < 128; k++)
            acc += y2[r * 129 + k] * fc3W[k * NCC + c];
        y3[r * NCC + c] = acc;
    }
    __syncthreads();
    if (t < NCC) {
        float s = 0.f, ss = 0.f;
#pragma unroll 8
        for (int r = 0; r < 64; r++) { float v = y3[r * NCC + t]; s += v; ss += v * v; }
        float mu = s * (1.f / GG);
        float var = ss * (1.f / GG) - mu * mu;
        sp[t] = mu;
        sp[64 + t] = rsqrtf(var + BNEPS) * fc3g[t];
    }
    __syncthreads();
    if (t < 640) {
        int r = t / NCC, c = t % NCC;
        out[t] = (y3[r * NCC + c] - sp[c]) * sp[64 + c] + fc3be[c];
    }
}

// ---------------- host orchestration ------------------------------------------
extern "C" void kernel_launch(void* const* d_in, const int* in_sizes, int n_in,
                              void* d_out, int out_size)
{
    const float* x      = (const float*)d_in[0];
    const int*   eidx   = (const int*)d_in[1];
    const int*   batch  = (const int*)d_in[2];
    const int*   sidx   = (const int*)d_in[3];
    const float* sattr  = (const float*)d_in[4];
    const float* gatW   = (const float*)d_in[5];
    const float* gasrc  = (const float*)d_in[6];
    const float* gadst  = (const float*)d_in[7];
    const float* gatb   = (const float*)d_in[8];
    const float* mlpW   = (const float*)d_in[9];
    const float* mlpg   = (const float*)d_in[11];
    const float* mlpbe  = (const float*)d_in[12];
    const float* fc1W   = (const float*)d_in[13];
    const float* fc1b   = (const float*)d_in[14];
    const float* fc1g   = (const float*)d_in[15];
    const float* fc1be  = (const float*)d_in[16];
    const float* fc2W   = (const float*)d_in[17];
    const float* fc2b   = (const float*)d_in[18];
    const float* fc2g   = (const float*)d_in[19];
    const float* fc2be  = (const float*)d_in[20];
    const float* fc3W   = (const float*)d_in[21];
    const float* fc3b   = (const float*)d_in[22];
    const float* fc3g   = (const float*)d_in[23];
    const float* fc3be  = (const float*)d_in[24];
    float* out = (float*)d_out;

    float* A;
    cudaGetSymbolAddress((void**)&A, g_arena);
    int* IA;
    cudaGetSymbolAddress((void**)&IA, g_iarena);

    float* B0   = A + O_B0;
    float* BR   = A + O_BR;
    float* X123 = A + O_X;
    float* H    = A + O_H;
    float* ATT  = A + O_ATT;
    float* AS   = A + O_AS;
    float* AD   = A + O_AD;
    float* MX   = A + O_MX;
    float* SEXP = A + O_SEXP;
    float* INV  = A + O_INV;
    float* CA   = A + O_CA;
    float* Z    = A + O_Z;
    float* ST   = A + O_STATS;
    float* POOL = A + O_POOL;

    int* DEG  = IA + I_DEG;
    int* CUR  = IA + I_CUR;
    int* RP   = IA + I_RP;
    int* CSRE = IA + I_CSRE;
    int* CSR0 = IA + I_CSR0;
    int* BSUM = IA + I_BSUM;

    static int configured = 0;
    if (!configured) {
        cudaFuncSetAttribute(k_head, cudaFuncAttributeMaxDynamicSharedMemorySize, 120 * 1024);
        cudaFuncSetAttribute(k_gemm_h_mma, cudaFuncAttributeMaxDynamicSharedMemorySize, 90 * 1024);
        configured = 1;
    }

    // ---- CSR builds (all 5 sets merged) ----
    cudaMemsetAsync(DEG, 0, 5 * NN * sizeof(int));
    cudaMemsetAsync(ST, 0, 512 * sizeof(float));
    cudaMemsetAsync(POOL, 0, (size_t)GG * FF * sizeof(float));
    dim3 h5(EGZ / 256, 5);
    k_hist5<<<h5, 256>>>(eidx, sidx, DEG);
    dim3 b5(NN / 256, 5);
    k_blocksum5<<<b5, 256>>>(DEG, BSUM);
    k_scanbs5<<<5, 128>>>(BSUM);
    k_scanout5<<<b5, 256>>>(DEG, BSUM, RP, CUR);
    dim3 f5(EGZ / 256, 5);
    k_fill5<<<f5, 256>>>(eidx, sidx, sattr, CUR, CSRE, CSR0, CA);

    // ---- gather stage (all CSR-based) ----
    dim3 gbr(NN * 16 / 256, 3);
    k_gatherBR<<<gbr, 256>>>(RP, DEG, CSR0, CA, x, BR);
    dim3 gg(NN * 16 / 256, 4);
    k_gather4<<<gg, 256>>>(RP, DEG, CSR0, CA, x, BR, B0, X123);

    const float* bx[4] = { B0, X123, X123 + NN * FF, X123 + 2 * NN * FF };

    const int smem1 = (64 * 68 + 64 * 264) * sizeof(float);

    // ---- 4 GAT branches ----
    for (int br = 0; br < 4; br++) {
        k_gemm_h_mma<<<NN / 64, 256, smem1>>>(bx[br], gatW + br * FF * HFD,
                                              gasrc + br * HH * FF, gadst + br * HH * FF,
                                              H, AS, AD);
        k_softmax<<<NN / 8, 256>>>(RP, DEG, CSRE, AS, AD, MX, SEXP, INV);
        k_aggr<<<NN * 64 / 256, 256>>>(RP, DEG, CSRE, AS, AD, MX, SEXP, INV, H, ATT);
        k_gemm_z_mma<<<NN / 64, 256>>>(ATT, gatb + br * HFD, mlpW + br * HFD * FF,
                                       Z + (size_t)br * NN * FF, ST + br * 128);
    }

    // ---- fused BN tail + pool ----
    k_bnfinal<<<NN * 16 / 256, 256>>>(Z, ST, mlpg, mlpbe, x, batch, POOL);

    // ---- fused head ----
    k_head<<<1, 1024, (64 * 65 + 64 * 257 + 64 * 129) * sizeof(float)>>>(
        POOL, fc1W, fc1b, fc1g, fc1be, fc2W, fc2b, fc2g, fc2be,
        fc3W, fc3b, fc3g, fc3be, out);
}